// round 2
// baseline (speedup 1.0000x reference)
#include <cuda_runtime.h>
#include <math.h>

#define HN 8      // heads
#define TN 2      // edge types
#define HT 16     // HN*TN
#define NB 16     // batch
#define EN 512    // entities
#define IND 1024  // in_dim
#define ON 128    // per-head dim
#define O2 256    // 2*ON
#define NEGV (-9.0e15f)

// ---------------- device scratch (no allocs allowed) ----------------
__device__ float g_h[(size_t)HT * NB * EN * ON];        // 67 MB: h[ht][n][e][o]
__device__ float g_gv1[HT * NB * ON];                   // g1 * a_src
__device__ float g_gv2[HT * NB * ON];                   // g2 * a_dst
__device__ float g_s1[HT * NB * EN];
__device__ float g_s2[HT * NB * EN];
__device__ float g_coefs[(size_t)HN * NB * EN * EN];    // 134 MB

// ====================================================================
// Kernel A: h[ht][row][o] = sum_d X[row][d] * W[ht][d][o]
//   X: (8192, 1024) row-major, W: (HT, 1024, 128)
//   grid (64, 1, 16), block 256; 128x128x16 tiles, 8x8 per thread
// ====================================================================
__global__ __launch_bounds__(256) void gemm_h_kernel(
    const float* __restrict__ X, const float* __restrict__ W)
{
    __shared__ float As[16][132];   // [k][m], padded
    __shared__ float Bs[16][128];   // [k][o]

    const int ht = blockIdx.z;
    const int m0 = blockIdx.x * 128;
    const float* Wp = W + (size_t)ht * IND * ON;
    const int tid = threadIdx.x;
    const int tx = tid & 15, ty = tid >> 4;

    float acc[8][8];
#pragma unroll
    for (int i = 0; i < 8; i++)
#pragma unroll
        for (int j = 0; j < 8; j++) acc[i][j] = 0.f;

    for (int k0 = 0; k0 < IND; k0 += 16) {
        // X tile: 128 rows x 16 k = 512 float4, 2 per thread; transpose to As[k][m]
#pragma unroll
        for (int l = 0; l < 2; l++) {
            int idx = tid * 2 + l;
            int r = idx >> 2;      // 0..127  (row within tile)
            int c4 = idx & 3;      // which float4 of the 16 k's
            float4 v = *(const float4*)(X + (size_t)(m0 + r) * IND + k0 + c4 * 4);
            As[c4 * 4 + 0][r] = v.x;
            As[c4 * 4 + 1][r] = v.y;
            As[c4 * 4 + 2][r] = v.z;
            As[c4 * 4 + 3][r] = v.w;
        }
        // W tile: 16 k x 128 o = 512 float4, 2 per thread, direct
#pragma unroll
        for (int l = 0; l < 2; l++) {
            int idx = tid * 2 + l;
            int k = idx >> 5;
            int c4 = idx & 31;
            *(float4*)&Bs[k][c4 * 4] =
                *(const float4*)(Wp + (size_t)(k0 + k) * ON + c4 * 4);
        }
        __syncthreads();
#pragma unroll
        for (int k = 0; k < 16; k++) {
            float a[8], b[8];
#pragma unroll
            for (int i = 0; i < 8; i++) a[i] = As[k][ty * 8 + i];
#pragma unroll
            for (int j = 0; j < 8; j++) b[j] = Bs[k][tx * 8 + j];
#pragma unroll
            for (int i = 0; i < 8; i++)
#pragma unroll
                for (int j = 0; j < 8; j++) acc[i][j] = fmaf(a[i], b[j], acc[i][j]);
        }
        __syncthreads();
    }

    float* Cp = g_h + (size_t)ht * NB * EN * ON;
#pragma unroll
    for (int i = 0; i < 8; i++) {
        int m = m0 + ty * 8 + i;
#pragma unroll
        for (int j4 = 0; j4 < 2; j4++) {
            float4 v = make_float4(acc[i][j4 * 4 + 0], acc[i][j4 * 4 + 1],
                                   acc[i][j4 * 4 + 2], acc[i][j4 * 4 + 3]);
            *(float4*)(Cp + (size_t)m * ON + tx * 8 + j4 * 4) = v;
        }
    }
}

// ====================================================================
// Kernel B: query-gate MLP.  grid 16 (ht), block 256.
//   c1 = relu(qv @ qW1[ht])    (16 x 256, K=1024)
//   g  = sigmoid(c1 @ qW2[ht]) (16 x 256, K=256)
//   gv1[ht][n][o] = g[n][o]     * a_src[ht][o]
//   gv2[ht][n][o] = g[n][O+o]   * a_dst[ht][o]
// ====================================================================
__global__ __launch_bounds__(256) void qgate_kernel(
    const float* __restrict__ qv, const float* __restrict__ qW1,
    const float* __restrict__ qW2, const float* __restrict__ a_src,
    const float* __restrict__ a_dst)
{
    __shared__ float qvs[NB][64];
    __shared__ float c1s[NB][O2];

    const int ht = blockIdx.x;
    const int t = threadIdx.x;   // 0..255, one output column each

    float acc[NB];
#pragma unroll
    for (int n = 0; n < NB; n++) acc[n] = 0.f;

    const float* W1 = qW1 + (size_t)ht * IND * O2;
    for (int q0 = 0; q0 < IND; q0 += 64) {
        {   // stage qv chunk: 16 x 64 = 256 float4, 1 per thread
            int n = t >> 4, c4 = t & 15;
            *(float4*)&qvs[n][c4 * 4] =
                *(const float4*)(qv + (size_t)n * IND + q0 + c4 * 4);
        }
        __syncthreads();
#pragma unroll 4
        for (int q = 0; q < 64; q++) {
            float w = W1[(size_t)(q0 + q) * O2 + t];
#pragma unroll
            for (int n = 0; n < NB; n++) acc[n] = fmaf(qvs[n][q], w, acc[n]);
        }
        __syncthreads();
    }
#pragma unroll
    for (int n = 0; n < NB; n++) c1s[n][t] = fmaxf(acc[n], 0.f);
    __syncthreads();

    float acc2[NB];
#pragma unroll
    for (int n = 0; n < NB; n++) acc2[n] = 0.f;
    const float* W2 = qW2 + (size_t)ht * O2 * O2;
    for (int c = 0; c < O2; c++) {
        float w = W2[(size_t)c * O2 + t];
#pragma unroll
        for (int n = 0; n < NB; n++) acc2[n] = fmaf(c1s[n][c], w, acc2[n]);
    }

    if (t < ON) {
        float av = a_src[ht * ON + t];
#pragma unroll
        for (int n = 0; n < NB; n++) {
            float sg = 1.f / (1.f + expf(-acc2[n]));
            g_gv1[((size_t)ht * NB + n) * ON + t] = sg * av;
        }
    } else {
        int o = t - ON;
        float av = a_dst[ht * ON + o];
#pragma unroll
        for (int n = 0; n < NB; n++) {
            float sg = 1.f / (1.f + expf(-acc2[n]));
            g_gv2[((size_t)ht * NB + n) * ON + o] = sg * av;
        }
    }
}

// ====================================================================
// Kernel C: s1[ht][n][e] = <h[ht][n][e][:], gv1[ht][n][:]>, same for s2
//   grid (EN/8, NB, HT), block 256 (8 warps, 1 e-row per warp)
// ====================================================================
__global__ __launch_bounds__(256) void svec_kernel()
{
    const int ht = blockIdx.z, n = blockIdx.y;
    const int warp = threadIdx.x >> 5, lane = threadIdx.x & 31;
    const int e = blockIdx.x * 8 + warp;

    const float* hp = g_h + (((size_t)ht * NB + n) * EN + e) * ON;
    const float* v1 = g_gv1 + ((size_t)ht * NB + n) * ON;
    const float* v2 = g_gv2 + ((size_t)ht * NB + n) * ON;

    float a1 = 0.f, a2 = 0.f;
#pragma unroll
    for (int r = 0; r < 4; r++) {
        float hv = hp[lane + r * 32];
        a1 = fmaf(hv, v1[lane + r * 32], a1);
        a2 = fmaf(hv, v2[lane + r * 32], a2);
    }
#pragma unroll
    for (int off = 16; off > 0; off >>= 1) {
        a1 += __shfl_xor_sync(0xffffffffu, a1, off);
        a2 += __shfl_xor_sync(0xffffffffu, a2, off);
    }
    if (lane == 0) {
        g_s1[((size_t)ht * NB + n) * EN + e] = a1;
        g_s2[((size_t)ht * NB + n) * EN + e] = a2;
    }
}

// ====================================================================
// Kernel D: per row (h,n,i): scores over j, masked by adj, softmax,
//           write coefs.  grid (EN, NB, HN), block 128 (4 j per thread)
// ====================================================================
__global__ __launch_bounds__(128) void softmax_kernel(const int* __restrict__ adj)
{
    const int i = blockIdx.x, n = blockIdx.y, h = blockIdx.z;
    const int t = threadIdx.x;
    const int warp = t >> 5, lane = t & 31;

    __shared__ float s2row[2][EN];
    __shared__ float red[8];

    for (int tt = 0; tt < 2; tt++)
        for (int j = t; j < EN; j += 128)
            s2row[tt][j] = g_s2[(((size_t)(h * 2 + tt) * NB) + n) * EN + j];

    float s1v0 = g_s1[(((size_t)(h * 2 + 0) * NB) + n) * EN + i];
    float s1v1 = g_s1[(((size_t)(h * 2 + 1) * NB) + n) * EN + i];
    __syncthreads();

    const int* arow = adj + ((size_t)n * EN + i) * EN;
    float v[4];
    float mx = NEGV;
#pragma unroll
    for (int r = 0; r < 4; r++) {
        int j = t + r * 128;
        int a = arow[j];
        float val;
        if (a > 0) {
            float x = (a == 1 ? s1v0 + s2row[0][j] : s1v1 + s2row[1][j]);
            val = x > 0.f ? x : 0.2f * x;
        } else {
            val = NEGV;
        }
        v[r] = val;
        mx = fmaxf(mx, val);
    }
    // block max
#pragma unroll
    for (int off = 16; off > 0; off >>= 1)
        mx = fmaxf(mx, __shfl_xor_sync(0xffffffffu, mx, off));
    if (lane == 0) red[warp] = mx;
    __syncthreads();
    mx = fmaxf(fmaxf(red[0], red[1]), fmaxf(red[2], red[3]));

    float sum = 0.f;
#pragma unroll
    for (int r = 0; r < 4; r++) {
        v[r] = expf(v[r] - mx);
        sum += v[r];
    }
#pragma unroll
    for (int off = 16; off > 0; off >>= 1)
        sum += __shfl_xor_sync(0xffffffffu, sum, off);
    if (lane == 0) red[4 + warp] = sum;
    __syncthreads();
    sum = red[4] + red[5] + red[6] + red[7];

    float inv = 1.f / sum;
    float* crow = g_coefs + ((((size_t)h * NB + n) * EN) + i) * EN;
#pragma unroll
    for (int r = 0; r < 4; r++) crow[t + r * 128] = v[r] * inv;
}

// ====================================================================
// Kernel E: per (h,n): Cout[j][o] = sum_i coefs[i][j] * h_last[i][o]
//   then out[n][j][h*128+o] = relu(Cout)
//   grid (EN/128=4, 1, HN*NB=128), block 256; both operands k-major
// ====================================================================
__global__ __launch_bounds__(256) void gemm_out_kernel(float* __restrict__ out)
{
    __shared__ float As[16][128];   // coefs[k=i][j]
    __shared__ float Bs[16][128];   // h_last[k=i][o]

    const int hn = blockIdx.z;
    const int h = hn / NB, n = hn % NB;
    const int j0 = blockIdx.x * 128;
    const float* Ap = g_coefs + (size_t)hn * EN * EN;
    const float* Bp = g_h + (((size_t)(h * TN + 1) * NB) + n) * EN * ON;
    const int tid = threadIdx.x;
    const int tx = tid & 15, ty = tid >> 4;

    float acc[8][8];
#pragma unroll
    for (int i = 0; i < 8; i++)
#pragma unroll
        for (int j = 0; j < 8; j++) acc[i][j] = 0.f;

    for (int k0 = 0; k0 < EN; k0 += 16) {
#pragma unroll
        for (int l = 0; l < 2; l++) {
            int idx = tid * 2 + l;
            int k = idx >> 5;
            int c4 = idx & 31;
            *(float4*)&As[k][c4 * 4] =
                *(const float4*)(Ap + (size_t)(k0 + k) * EN + j0 + c4 * 4);
            *(float4*)&Bs[k][c4 * 4] =
                *(const float4*)(Bp + (size_t)(k0 + k) * ON + c4 * 4);
        }
        __syncthreads();
#pragma unroll
        for (int k = 0; k < 16; k++) {
            float a[8], b[8];
#pragma unroll
            for (int i = 0; i < 8; i++) a[i] = As[k][ty * 8 + i];
#pragma unroll
            for (int j = 0; j < 8; j++) b[j] = Bs[k][tx * 8 + j];
#pragma unroll
            for (int i = 0; i < 8; i++)
#pragma unroll
                for (int j = 0; j < 8; j++) acc[i][j] = fmaf(a[i], b[j], acc[i][j]);
        }
        __syncthreads();
    }

#pragma unroll
    for (int i = 0; i < 8; i++) {
        int j = j0 + ty * 8 + i;
        float* op = out + ((size_t)n * EN + j) * (HN * ON) + h * ON + tx * 8;
#pragma unroll
        for (int j4 = 0; j4 < 2; j4++) {
            float4 v = make_float4(fmaxf(acc[i][j4 * 4 + 0], 0.f),
                                   fmaxf(acc[i][j4 * 4 + 1], 0.f),
                                   fmaxf(acc[i][j4 * 4 + 2], 0.f),
                                   fmaxf(acc[i][j4 * 4 + 3], 0.f));
            *(float4*)(op + j4 * 4) = v;
        }
    }
}

// ====================================================================
extern "C" void kernel_launch(void* const* d_in, const int* in_sizes, int n_in,
                              void* d_out, int out_size)
{
    const float* input_state = (const float*)d_in[0]; // (16,512,1024)
    const int*   adj         = (const int*)d_in[1];   // (16,512,512)
    // d_in[2] entity_mask: unused by reference
    const float* query_vec   = (const float*)d_in[3]; // (16,1024)
    const float* W           = (const float*)d_in[4]; // (8,2,1024,128)
    const float* a_src       = (const float*)d_in[5]; // (8,2,128)
    const float* a_dst       = (const float*)d_in[6]; // (8,2,128)
    const float* qW1         = (const float*)d_in[7]; // (8,2,1024,256)
    const float* qW2         = (const float*)d_in[8]; // (8,2,256,256)
    float* out = (float*)d_out;                       // (16,512,1024)

    // A: h projection GEMM (independent of B)
    gemm_h_kernel<<<dim3(64, 1, HT), 256>>>(input_state, W);
    // B: query gate MLP
    qgate_kernel<<<HT, 256>>>(query_vec, qW1, qW2, a_src, a_dst);
    // C: s1/s2 per-entity dots
    svec_kernel<<<dim3(EN / 8, NB, HT), 256>>>();
    // D: masked scores + softmax -> coefs
    softmax_kernel<<<dim3(EN, NB, HN), 128>>>(adj);
    // E: attention aggregation GEMM + relu + transpose
    gemm_out_kernel<<<dim3(EN / 128, 1, HN * NB), 256>>>(out);
}

// round 6
// speedup vs baseline: 2.2627x; 2.2627x over previous
#include <cuda_runtime.h>
#include <math.h>
#include <stdint.h>

#define HN 8      // heads
#define TN 2      // edge types
#define HT 16     // HN*TN
#define NB 16     // batch
#define EN 512    // entities
#define IND 1024  // in_dim
#define ON 128    // per-head dim
#define O2 256    // 2*ON
#define NEGV (-9.0e15f)

// ---------------- device scratch (no allocs allowed) ----------------
__device__ float g_h[(size_t)HT * NB * EN * ON];        // 67 MB: h[ht][n][e][o]
__device__ float g_gv1[HT * NB * ON];                   // g1 * a_src
__device__ float g_gv2[HT * NB * ON];                   // g2 * a_dst
__device__ float g_s1[HT * NB * EN];
__device__ float g_s2[HT * NB * EN];
__device__ float g_coefs[(size_t)HN * NB * EN * EN];    // 134 MB

// ---------------- mma helpers ----------------
__device__ __forceinline__ uint32_t f2tf(float x) {
    uint32_t r;
    asm("cvt.rna.tf32.f32 %0, %1;" : "=r"(r) : "f"(x));
    return r;
}

__device__ __forceinline__ void mma_tf32(float4& c, const uint32_t a[4],
                                         const uint32_t b[2]) {
    asm volatile(
        "mma.sync.aligned.m16n8k8.row.col.f32.tf32.tf32.f32 "
        "{%0,%1,%2,%3}, {%4,%5,%6,%7}, {%8,%9}, {%0,%1,%2,%3};"
        : "+f"(c.x), "+f"(c.y), "+f"(c.z), "+f"(c.w)
        : "r"(a[0]), "r"(a[1]), "r"(a[2]), "r"(a[3]), "r"(b[0]), "r"(b[1]));
}

__device__ __forceinline__ void cpa16(uint32_t dst, const float* src) {
    asm volatile("cp.async.cg.shared.global [%0], [%1], 16;" ::"r"(dst), "l"(src));
}
#define CP_COMMIT() asm volatile("cp.async.commit_group;")
#define CP_WAIT(n)  asm volatile("cp.async.wait_group %0;" ::"n"(n))

// ====================================================================
// Kernel A (tf32 mma): h[ht][m][o] = sum_d X[m][d] * W[ht][d][o]
//   M = NB*EN = 8192 per ht, N = 128, K = 1024
//   block 256 (8 warps, 2x4 -> 64x32 warp tiles), tile 128x128x32
//   As: [m][k] padded 36, Bs: [k][n] padded 132.  2-stage cp.async.
// ====================================================================
#define A_ST  (128 * 36)
#define B_ST  (32 * 132)
#define STG_H (A_ST + B_ST)

// load one 128x32 X tile (transposed-free, [m][k]) + one 32x128 W tile ([k][n])
__device__ __forceinline__ void stage_h(uint32_t ub, int so,
                                        const float* __restrict__ X,
                                        const float* __restrict__ Wp,
                                        int m0, int k0, int tid)
{
    // A: 128 rows x 32 k = 1024 float4
#pragma unroll
    for (int l = 0; l < 4; l++) {
        int idx = tid + l * 256;
        int r = idx >> 3, c = (idx & 7) * 4;       // 8 float4 per row
        cpa16(ub + (so + r * 36 + c) * 4, X + (size_t)(m0 + r) * IND + k0 + c);
    }
    // B: 32 rows x 128 n = 1024 float4
#pragma unroll
    for (int l = 0; l < 4; l++) {
        int idx = tid + l * 256;
        int r = idx >> 5, c = (idx & 31) * 4;      // 32 float4 per row
        cpa16(ub + (so + A_ST + r * 132 + c) * 4, Wp + (size_t)(k0 + r) * ON + c);
    }
}

__global__ __launch_bounds__(256) void gemm_h_mma(
    const float* __restrict__ X, const float* __restrict__ W)
{
    extern __shared__ __align__(16) float sm[];
    const uint32_t ub = (uint32_t)__cvta_generic_to_shared(sm);

    const int ht = blockIdx.z;
    const int m0 = blockIdx.x * 128;
    const float* Wp = W + (size_t)ht * IND * ON;
    const int tid = threadIdx.x;
    const int lane = tid & 31, w = tid >> 5;
    const int gid = lane >> 2, tig = lane & 3;
    const int mbase = (w >> 2) * 64, nbase = (w & 3) * 32;

    float4 acc[4][4];
#pragma unroll
    for (int i = 0; i < 4; i++)
#pragma unroll
        for (int j = 0; j < 4; j++) acc[i][j] = make_float4(0.f, 0.f, 0.f, 0.f);

    const int NC = IND / 32;

    stage_h(ub, 0, X, Wp, m0, 0, tid);
    CP_COMMIT();

    for (int kc = 0; kc < NC; kc++) {
        if (kc + 1 < NC) {
            stage_h(ub, ((kc + 1) & 1) * STG_H, X, Wp, m0, (kc + 1) * 32, tid);
            CP_COMMIT();
            CP_WAIT(1);
        } else {
            CP_WAIT(0);
        }
        __syncthreads();

        const float* As = sm + (kc & 1) * STG_H;
        const float* Bs = As + A_ST;
#pragma unroll
        for (int ks = 0; ks < 4; ks++) {
            const int k0 = ks * 8;
            uint32_t a[4][4], b[4][2];
#pragma unroll
            for (int mt = 0; mt < 4; mt++) {
                int mr = mbase + mt * 16;
                a[mt][0] = f2tf(As[(mr + gid) * 36 + k0 + tig]);
                a[mt][1] = f2tf(As[(mr + 8 + gid) * 36 + k0 + tig]);
                a[mt][2] = f2tf(As[(mr + gid) * 36 + k0 + tig + 4]);
                a[mt][3] = f2tf(As[(mr + 8 + gid) * 36 + k0 + tig + 4]);
            }
#pragma unroll
            for (int nt = 0; nt < 4; nt++) {
                int nc = nbase + nt * 8 + gid;
                b[nt][0] = f2tf(Bs[(k0 + tig) * 132 + nc]);
                b[nt][1] = f2tf(Bs[(k0 + tig + 4) * 132 + nc]);
            }
#pragma unroll
            for (int mt = 0; mt < 4; mt++)
#pragma unroll
                for (int nt = 0; nt < 4; nt++) mma_tf32(acc[mt][nt], a[mt], b[nt]);
        }
        __syncthreads();
    }

    float* Cp = g_h + (size_t)ht * NB * EN * ON + (size_t)m0 * ON;
#pragma unroll
    for (int mt = 0; mt < 4; mt++) {
        int r0 = mbase + mt * 16 + gid;
#pragma unroll
        for (int nt = 0; nt < 4; nt++) {
            int c = nbase + nt * 8 + 2 * tig;
            float4 v = acc[mt][nt];
            *(float2*)(Cp + (size_t)r0 * ON + c)       = make_float2(v.x, v.y);
            *(float2*)(Cp + (size_t)(r0 + 8) * ON + c) = make_float2(v.z, v.w);
        }
    }
}

// ====================================================================
// Kernel E (tf32 mma): per (h,n): Cout[j][o] = sum_i coefs[i][j]*h_last[i][o]
//   M = 512 (j), N = 128 (o), K = 512 (i). A = coefs (k-major), B = h_last.
//   grid (4, 1, 128), block 256.  relu + transposed store.
// ====================================================================
#define A2_ST (32 * 132)
#define STG_O (2 * A2_ST)

__device__ __forceinline__ void stage_o(uint32_t ub, int so,
                                        const float* __restrict__ Ap,
                                        const float* __restrict__ Bp,
                                        int m0, int k0, int tid)
{
    // A: 32 k-rows x 128 j = 1024 float4
#pragma unroll
    for (int l = 0; l < 4; l++) {
        int idx = tid + l * 256;
        int r = idx >> 5, c = (idx & 31) * 4;
        cpa16(ub + (so + r * 132 + c) * 4, Ap + (size_t)(k0 + r) * EN + m0 + c);
    }
    // B: 32 k-rows x 128 o = 1024 float4
#pragma unroll
    for (int l = 0; l < 4; l++) {
        int idx = tid + l * 256;
        int r = idx >> 5, c = (idx & 31) * 4;
        cpa16(ub + (so + A2_ST + r * 132 + c) * 4, Bp + (size_t)(k0 + r) * ON + c);
    }
}

__global__ __launch_bounds__(256) void gemm_out_mma(float* __restrict__ out)
{
    extern __shared__ __align__(16) float sm[];
    const uint32_t ub = (uint32_t)__cvta_generic_to_shared(sm);

    const int hn = blockIdx.z;
    const int h = hn / NB, n = hn % NB;
    const int m0 = blockIdx.x * 128;
    const float* Ap = g_coefs + (size_t)hn * EN * EN;                     // [i][j]
    const float* Bp = g_h + (((size_t)(h * TN + 1) * NB) + n) * EN * ON;  // [i][o]

    const int tid = threadIdx.x;
    const int lane = tid & 31, w = tid >> 5;
    const int gid = lane >> 2, tig = lane & 3;
    const int mbase = (w >> 2) * 64, nbase = (w & 3) * 32;

    float4 acc[4][4];
#pragma unroll
    for (int i = 0; i < 4; i++)
#pragma unroll
        for (int j = 0; j < 4; j++) acc[i][j] = make_float4(0.f, 0.f, 0.f, 0.f);

    const int NC = EN / 32;

    stage_o(ub, 0, Ap, Bp, m0, 0, tid);
    CP_COMMIT();

    for (int kc = 0; kc < NC; kc++) {
        if (kc + 1 < NC) {
            stage_o(ub, ((kc + 1) & 1) * STG_O, Ap, Bp, m0, (kc + 1) * 32, tid);
            CP_COMMIT();
            CP_WAIT(1);
        } else {
            CP_WAIT(0);
        }
        __syncthreads();

        const float* As = sm + (kc & 1) * STG_O;  // [k][j] (k-major)
        const float* Bs = As + A2_ST;             // [k][o]
#pragma unroll
        for (int ks = 0; ks < 4; ks++) {
            const int k0 = ks * 8;
            uint32_t a[4][4], b[4][2];
#pragma unroll
            for (int mt = 0; mt < 4; mt++) {
                int mr = mbase + mt * 16;
                a[mt][0] = f2tf(As[(k0 + tig) * 132 + mr + gid]);
                a[mt][1] = f2tf(As[(k0 + tig) * 132 + mr + 8 + gid]);
                a[mt][2] = f2tf(As[(k0 + tig + 4) * 132 + mr + gid]);
                a[mt][3] = f2tf(As[(k0 + tig + 4) * 132 + mr + 8 + gid]);
            }
#pragma unroll
            for (int nt = 0; nt < 4; nt++) {
                int nc = nbase + nt * 8 + gid;
                b[nt][0] = f2tf(Bs[(k0 + tig) * 132 + nc]);
                b[nt][1] = f2tf(Bs[(k0 + tig + 4) * 132 + nc]);
            }
#pragma unroll
            for (int mt = 0; mt < 4; mt++)
#pragma unroll
                for (int nt = 0; nt < 4; nt++) mma_tf32(acc[mt][nt], a[mt], b[nt]);
        }
        __syncthreads();
    }

#pragma unroll
    for (int mt = 0; mt < 4; mt++) {
        int j0 = m0 + mbase + mt * 16 + gid;
#pragma unroll
        for (int nt = 0; nt < 4; nt++) {
            int c = nbase + nt * 8 + 2 * tig;
            float4 v = acc[mt][nt];
            float* p0 = out + ((size_t)n * EN + j0) * (HN * ON) + h * ON + c;
            float* p1 = out + ((size_t)n * EN + j0 + 8) * (HN * ON) + h * ON + c;
            *(float2*)p0 = make_float2(fmaxf(v.x, 0.f), fmaxf(v.y, 0.f));
            *(float2*)p1 = make_float2(fmaxf(v.z, 0.f), fmaxf(v.w, 0.f));
        }
    }
}

// ====================================================================
// Kernel B: query-gate MLP.  grid 16 (ht), block 256.
// ====================================================================
__global__ __launch_bounds__(256) void qgate_kernel(
    const float* __restrict__ qv, const float* __restrict__ qW1,
    const float* __restrict__ qW2, const float* __restrict__ a_src,
    const float* __restrict__ a_dst)
{
    __shared__ float qvs[NB][64];
    __shared__ float c1s[NB][O2];

    const int ht = blockIdx.x;
    const int t = threadIdx.x;

    float acc[NB];
#pragma unroll
    for (int n = 0; n < NB; n++) acc[n] = 0.f;

    const float* W1 = qW1 + (size_t)ht * IND * O2;
    for (int q0 = 0; q0 < IND; q0 += 64) {
        {
            int n = t >> 4, c4 = t & 15;
            *(float4*)&qvs[n][c4 * 4] =
                *(const float4*)(qv + (size_t)n * IND + q0 + c4 * 4);
        }
        __syncthreads();
#pragma unroll 4
        for (int q = 0; q < 64; q++) {
            float w = W1[(size_t)(q0 + q) * O2 + t];
#pragma unroll
            for (int n = 0; n < NB; n++) acc[n] = fmaf(qvs[n][q], w, acc[n]);
        }
        __syncthreads();
    }
#pragma unroll
    for (int n = 0; n < NB; n++) c1s[n][t] = fmaxf(acc[n], 0.f);
    __syncthreads();

    float acc2[NB];
#pragma unroll
    for (int n = 0; n < NB; n++) acc2[n] = 0.f;
    const float* W2 = qW2 + (size_t)ht * O2 * O2;
    for (int c = 0; c < O2; c++) {
        float w = W2[(size_t)c * O2 + t];
#pragma unroll
        for (int n = 0; n < NB; n++) acc2[n] = fmaf(c1s[n][c], w, acc2[n]);
    }

    if (t < ON) {
        float av = a_src[ht * ON + t];
#pragma unroll
        for (int n = 0; n < NB; n++) {
            float sg = 1.f / (1.f + expf(-acc2[n]));
            g_gv1[((size_t)ht * NB + n) * ON + t] = sg * av;
        }
    } else {
        int o = t - ON;
        float av = a_dst[ht * ON + o];
#pragma unroll
        for (int n = 0; n < NB; n++) {
            float sg = 1.f / (1.f + expf(-acc2[n]));
            g_gv2[((size_t)ht * NB + n) * ON + o] = sg * av;
        }
    }
}

// ====================================================================
// Kernel C: s1[ht][n][e] = <h[ht][n][e][:], gv1[ht][n][:]>, same for s2
// ====================================================================
__global__ __launch_bounds__(256) void svec_kernel()
{
    const int ht = blockIdx.z, n = blockIdx.y;
    const int warp = threadIdx.x >> 5, lane = threadIdx.x & 31;
    const int e = blockIdx.x * 8 + warp;

    const float* hp = g_h + (((size_t)ht * NB + n) * EN + e) * ON;
    const float* v1 = g_gv1 + ((size_t)ht * NB + n) * ON;
    const float* v2 = g_gv2 + ((size_t)ht * NB + n) * ON;

    float a1 = 0.f, a2 = 0.f;
#pragma unroll
    for (int r = 0; r < 4; r++) {
        float hv = hp[lane + r * 32];
        a1 = fmaf(hv, v1[lane + r * 32], a1);
        a2 = fmaf(hv, v2[lane + r * 32], a2);
    }
#pragma unroll
    for (int off = 16; off > 0; off >>= 1) {
        a1 += __shfl_xor_sync(0xffffffffu, a1, off);
        a2 += __shfl_xor_sync(0xffffffffu, a2, off);
    }
    if (lane == 0) {
        g_s1[((size_t)ht * NB + n) * EN + e] = a1;
        g_s2[((size_t)ht * NB + n) * EN + e] = a2;
    }
}

// ====================================================================
// Kernel D: per (i,n): one warp per head. adj row loaded once per block.
//   grid (EN, NB), block 256 (8 warps = 8 heads)
// ====================================================================
__global__ __launch_bounds__(256) void softmax_kernel2(const int* __restrict__ adj)
{
    const int i = blockIdx.x, n = blockIdx.y;
    const int h = threadIdx.x >> 5, lane = threadIdx.x & 31;

    __shared__ int arow_s[EN];
    for (int j = threadIdx.x; j < EN; j += 256)
        arow_s[j] = adj[((size_t)n * EN + i) * EN + j];
    __syncthreads();

    const float s1v0 = g_s1[((size_t)(h * 2 + 0) * NB + n) * EN + i];
    const float s1v1 = g_s1[((size_t)(h * 2 + 1) * NB + n) * EN + i];
    const float* s20 = g_s2 + ((size_t)(h * 2 + 0) * NB + n) * EN;
    const float* s21 = g_s2 + ((size_t)(h * 2 + 1) * NB + n) * EN;

    float v[16];
    float mx = NEGV;
#pragma unroll
    for (int r = 0; r < 16; r++) {
        int j = lane + r * 32;
        int a = arow_s[j];
        float val = NEGV;
        if (a > 0) {
            float x = (a == 1) ? s1v0 + s20[j] : s1v1 + s21[j];
            val = x > 0.f ? x : 0.2f * x;
        }
        v[r] = val;
        mx = fmaxf(mx, val);
    }
#pragma unroll
    for (int off = 16; off > 0; off >>= 1)
        mx = fmaxf(mx, __shfl_xor_sync(0xffffffffu, mx, off));

    float sum = 0.f;
#pragma unroll
    for (int r = 0; r < 16; r++) {
        v[r] = expf(v[r] - mx);
        sum += v[r];
    }
#pragma unroll
    for (int off = 16; off > 0; off >>= 1)
        sum += __shfl_xor_sync(0xffffffffu, sum, off);

    const float inv = 1.f / sum;
    float* crow = g_coefs + (((size_t)h * NB + n) * EN + i) * EN;
#pragma unroll
    for (int r = 0; r < 16; r++) crow[lane + r * 32] = v[r] * inv;
}

// ====================================================================
extern "C" void kernel_launch(void* const* d_in, const int* in_sizes, int n_in,
                              void* d_out, int out_size)
{
    const float* input_state = (const float*)d_in[0]; // (16,512,1024)
    const int*   adj         = (const int*)d_in[1];   // (16,512,512)
    const float* query_vec   = (const float*)d_in[3]; // (16,1024)
    const float* W           = (const float*)d_in[4]; // (8,2,1024,128)
    const float* a_src       = (const float*)d_in[5]; // (8,2,128)
    const float* a_dst       = (const float*)d_in[6]; // (8,2,128)
    const float* qW1         = (const float*)d_in[7]; // (8,2,1024,256)
    const float* qW2         = (const float*)d_in[8]; // (8,2,256,256)
    float* out = (float*)d_out;                       // (16,512,1024)

    const int SMEM_H = 2 * STG_H * 4;  // 70656 B
    const int SMEM_O = 2 * STG_O * 4;  // 67584 B
    cudaFuncSetAttribute(gemm_h_mma, cudaFuncAttributeMaxDynamicSharedMemorySize, SMEM_H);
    cudaFuncSetAttribute(gemm_out_mma, cudaFuncAttributeMaxDynamicSharedMemorySize, SMEM_O);

    gemm_h_mma<<<dim3(64, 1, HT), 256, SMEM_H>>>(input_state, W);
    qgate_kernel<<<HT, 256>>>(query_vec, qW1, qW2, a_src, a_dst);
    svec_kernel<<<dim3(EN / 8, NB, HT), 256>>>();
    softmax_kernel2<<<dim3(EN, NB), 256>>>(adj);
    gemm_out_mma<<<dim3(EN / 128, 1, HN * NB), 256, SMEM_O>>>(out);
}